// round 3
// baseline (speedup 1.0000x reference)
#include <cuda_runtime.h>
#include <math.h>

#define H    1024
#define F    2816
#define E    8
#define NTOK 2048
#define MAXK 2            // dataset fixes top_k = 2; scratch sized for this

#define BM 128
#define BN 128
#define BK 8
#define TM 8
#define TN 8

// ---------------- device scratch (static, no allocation) ----------------
__device__ int   g_count[E];
__device__ int   g_offs[E];
__device__ int   g_tok[E * NTOK];
__device__ float g_wt [E * NTOK];
// activation scratch: MAXK * NTOK rows of F floats (~46 MB, bss)
__device__ float g_act[(size_t)MAXK * NTOK * F];

// ---------------- helpers ----------------
__global__ void zero_counts_kernel() {
    if (threadIdx.x < E) g_count[threadIdx.x] = 0;
}

__global__ void offs_kernel() {
    if (threadIdx.x == 0) {
        int o = 0;
        for (int e = 0; e < E; e++) { g_offs[e] = o; o += g_count[e]; }
    }
}

// ---------------- router: logits -> softmax -> top-k -> scatter ----------------
__global__ __launch_bounds__(256) void router_kernel(const float* __restrict__ x,
                                                     const float* __restrict__ gw,
                                                     const int* __restrict__ topk_ptr) {
    const int token = blockIdx.x;
    const float* xr = x + (size_t)token * H;

    float p[E];
#pragma unroll
    for (int e = 0; e < E; e++) p[e] = 0.f;

    for (int h = threadIdx.x; h < H; h += blockDim.x) {
        const float xv = xr[h];
#pragma unroll
        for (int e = 0; e < E; e++) p[e] += xv * gw[e * H + h];
    }

    // warp reduce each accumulator
#pragma unroll
    for (int e = 0; e < E; e++)
#pragma unroll
        for (int o = 16; o > 0; o >>= 1) p[e] += __shfl_xor_sync(0xffffffffu, p[e], o);

    __shared__ float sp[8][E];
    const int warp = threadIdx.x >> 5;
    const int lane = threadIdx.x & 31;
    if (lane == 0) {
#pragma unroll
        for (int e = 0; e < E; e++) sp[warp][e] = p[e];
    }
    __syncthreads();

    if (threadIdx.x == 0) {
        float lg[E];
#pragma unroll
        for (int e = 0; e < E; e++) {
            float s = 0.f;
            for (int w = 0; w < 8; w++) s += sp[w][e];
            lg[e] = s;
        }
        // softmax
        float mx = lg[0];
#pragma unroll
        for (int e = 1; e < E; e++) mx = fmaxf(mx, lg[e]);
        float pr[E]; float psum = 0.f;
#pragma unroll
        for (int e = 0; e < E; e++) { pr[e] = expf(lg[e] - mx); psum += pr[e]; }
#pragma unroll
        for (int e = 0; e < E; e++) pr[e] /= psum;

        int k = topk_ptr[0];
        if (k < 1) k = 1;
        if (k > MAXK) k = MAXK;

        // top-k, ties -> lower index (matches jax.lax.top_k)
        bool used[E];
#pragma unroll
        for (int e = 0; e < E; e++) used[e] = false;
        int   sel[MAXK];
        float sw[MAXK];
        float ssum = 0.f;
        for (int j = 0; j < k; j++) {
            int best = -1; float bv = -1.f;
            for (int e = 0; e < E; e++)
                if (!used[e] && pr[e] > bv) { bv = pr[e]; best = e; }
            used[best] = true; sel[j] = best; sw[j] = bv; ssum += bv;
        }
        const float inv = 1.f / ssum;
        for (int j = 0; j < k; j++) {
            const int ee = sel[j];
            const int pos = atomicAdd(&g_count[ee], 1);
            g_tok[ee * NTOK + pos] = token;
            g_wt [ee * NTOK + pos] = sw[j] * inv;
        }
    }
}

// ---------------- GEMM 1: act = silu(Xg @ w1[e]^T), gathered rows ----------------
__global__ __launch_bounds__(256) void gemm_up_kernel(const float* __restrict__ x,
                                                      const float* __restrict__ w1) {
    const int e   = blockIdx.z;
    const int cnt = g_count[e];
    const int m0  = blockIdx.y * BM;
    if (m0 >= cnt) return;
    const int n0   = blockIdx.x * BN;
    const int base = g_offs[e];

    __shared__ float As[BK][BM];
    __shared__ float Bs[BK][BN];

    const int tid = threadIdx.x;
    const int tr  = tid >> 4;        // 0..15
    const int tc  = tid & 15;        // 0..15
    const int lrow = tid >> 1;       // 0..127
    const int lcol = (tid & 1) << 2; // 0 or 4

    const float* aptr = nullptr;
    {
        const int gm = m0 + lrow;
        if (gm < cnt) aptr = x + (size_t)g_tok[e * NTOK + gm] * H + lcol;
    }
    const float* bptr = w1 + ((size_t)e * F + (size_t)(n0 + lrow)) * H + lcol;

    float acc[TM][TN];
#pragma unroll
    for (int i = 0; i < TM; i++)
#pragma unroll
        for (int j = 0; j < TN; j++) acc[i][j] = 0.f;

    for (int kb = 0; kb < H; kb += BK) {
        float4 av = make_float4(0.f, 0.f, 0.f, 0.f);
        if (aptr) av = *(const float4*)(aptr + kb);
        const float4 bv = *(const float4*)(bptr + kb);
        __syncthreads();
        As[lcol + 0][lrow] = av.x; As[lcol + 1][lrow] = av.y;
        As[lcol + 2][lrow] = av.z; As[lcol + 3][lrow] = av.w;
        Bs[lcol + 0][lrow] = bv.x; Bs[lcol + 1][lrow] = bv.y;
        Bs[lcol + 2][lrow] = bv.z; Bs[lcol + 3][lrow] = bv.w;
        __syncthreads();
#pragma unroll
        for (int k = 0; k < BK; k++) {
            const float4 a0 = *(const float4*)&As[k][tr * TM];
            const float4 a1 = *(const float4*)&As[k][tr * TM + 4];
            const float4 b0 = *(const float4*)&Bs[k][tc * TN];
            const float4 b1 = *(const float4*)&Bs[k][tc * TN + 4];
            const float a[TM] = {a0.x, a0.y, a0.z, a0.w, a1.x, a1.y, a1.z, a1.w};
            const float b[TN] = {b0.x, b0.y, b0.z, b0.w, b1.x, b1.y, b1.z, b1.w};
#pragma unroll
            for (int i = 0; i < TM; i++)
#pragma unroll
                for (int j = 0; j < TN; j++) acc[i][j] += a[i] * b[j];
        }
    }

#pragma unroll
    for (int i = 0; i < TM; i++) {
        const int m = m0 + tr * TM + i;
        if (m < cnt) {
            float* dst = g_act + (size_t)(base + m) * F + n0 + tc * TN;
#pragma unroll
            for (int j = 0; j < TN; j++) {
                const float v = acc[i][j];
                dst[j] = v / (1.f + expf(-v));   // silu
            }
        }
    }
}

// ---------------- GEMM 2: out[tok] += wt * (act @ w2[e]^T) ----------------
__global__ __launch_bounds__(256) void gemm_down_kernel(const float* __restrict__ w2,
                                                        float* __restrict__ out) {
    const int e   = blockIdx.z;
    const int cnt = g_count[e];
    const int m0  = blockIdx.y * BM;
    if (m0 >= cnt) return;
    const int n0   = blockIdx.x * BN;
    const int base = g_offs[e];

    __shared__ float As[BK][BM];
    __shared__ float Bs[BK][BN];

    const int tid = threadIdx.x;
    const int tr  = tid >> 4;
    const int tc  = tid & 15;
    const int lrow = tid >> 1;
    const int lcol = (tid & 1) << 2;

    const float* aptr = nullptr;
    {
        const int gm = m0 + lrow;
        if (gm < cnt) aptr = g_act + (size_t)(base + gm) * F + lcol;
    }
    const float* bptr = w2 + ((size_t)e * H + (size_t)(n0 + lrow)) * F + lcol;

    float acc[TM][TN];
#pragma unroll
    for (int i = 0; i < TM; i++)
#pragma unroll
        for (int j = 0; j < TN; j++) acc[i][j] = 0.f;

    for (int kb = 0; kb < F; kb += BK) {
        float4 av = make_float4(0.f, 0.f, 0.f, 0.f);
        if (aptr) av = *(const float4*)(aptr + kb);
        const float4 bv = *(const float4*)(bptr + kb);
        __syncthreads();
        As[lcol + 0][lrow] = av.x; As[lcol + 1][lrow] = av.y;
        As[lcol + 2][lrow] = av.z; As[lcol + 3][lrow] = av.w;
        Bs[lcol + 0][lrow] = bv.x; Bs[lcol + 1][lrow] = bv.y;
        Bs[lcol + 2][lrow] = bv.z; Bs[lcol + 3][lrow] = bv.w;
        __syncthreads();
#pragma unroll
        for (int k = 0; k < BK; k++) {
            const float4 a0 = *(const float4*)&As[k][tr * TM];
            const float4 a1 = *(const float4*)&As[k][tr * TM + 4];
            const float4 b0 = *(const float4*)&Bs[k][tc * TN];
            const float4 b1 = *(const float4*)&Bs[k][tc * TN + 4];
            const float a[TM] = {a0.x, a0.y, a0.z, a0.w, a1.x, a1.y, a1.z, a1.w};
            const float b[TN] = {b0.x, b0.y, b0.z, b0.w, b1.x, b1.y, b1.z, b1.w};
#pragma unroll
            for (int i = 0; i < TM; i++)
#pragma unroll
                for (int j = 0; j < TN; j++) acc[i][j] += a[i] * b[j];
        }
    }

#pragma unroll
    for (int i = 0; i < TM; i++) {
        const int m = m0 + tr * TM + i;
        if (m < cnt) {
            const int   tok = g_tok[e * NTOK + m];
            const float wt  = g_wt [e * NTOK + m];
            float* dst = out + (size_t)tok * H + n0 + tc * TN;
#pragma unroll
            for (int j = 0; j < TN; j++)
                atomicAdd(&dst[j], acc[i][j] * wt);
        }
    }
}

// ---------------- launch ----------------
extern "C" void kernel_launch(void* const* d_in, const int* in_sizes, int n_in,
                              void* d_out, int out_size) {
    const float* x   = (const float*)d_in[0];
    const float* gw  = (const float*)d_in[1];
    const float* w1  = (const float*)d_in[2];
    const float* w2  = (const float*)d_in[3];
    const int*   tk  = (const int*)d_in[4];
    float* out = (float*)d_out;

    cudaMemsetAsync(out, 0, (size_t)out_size * sizeof(float));
    zero_counts_kernel<<<1, 32>>>();
    router_kernel<<<NTOK, 256>>>(x, gw, tk);
    offs_kernel<<<1, 32>>>();

    dim3 gup(F / BN, NTOK / BM, E);
    gemm_up_kernel<<<gup, 256>>>(x, w1);

    dim3 gdn(H / BN, NTOK / BM, E);
    gemm_down_kernel<<<gdn, 256>>>(w2, out);
}

// round 7
// speedup vs baseline: 2.3024x; 2.3024x over previous
#include <cuda_runtime.h>
#include <math.h>
#include <stdint.h>

#define H    1024
#define F    2816
#define E    8
#define NTOK 2048
#define MAXK 2

#define BM 128
#define BN 128
#define BK 32
#define SPAD 36          // smem row stride (floats), conflict-avoiding pad

// ---------------- device scratch ----------------
__device__ int   g_count[E];
__device__ int   g_offs[E];
__device__ int   g_tok[E * NTOK];
__device__ float g_wt [E * NTOK];
__device__ float g_act[(size_t)MAXK * NTOK * F];

// ---------------- helpers ----------------
__device__ __forceinline__ float to_tf32(float x) {
    float r; asm("cvt.rna.tf32.f32 %0, %1;" : "=f"(r) : "f"(x)); return r;
}

#define MMA_TF32(c, a, b)                                                        \
    asm volatile("mma.sync.aligned.m16n8k8.row.col.f32.tf32.tf32.f32 "           \
        "{%0,%1,%2,%3}, {%4,%5,%6,%7}, {%8,%9}, {%0,%1,%2,%3};"                  \
        : "+f"((c)[0]), "+f"((c)[1]), "+f"((c)[2]), "+f"((c)[3])                 \
        : "r"((a)[0]), "r"((a)[1]), "r"((a)[2]), "r"((a)[3]),                    \
          "r"((b)[0]), "r"((b)[1]))

__global__ void zero_counts_kernel() { if (threadIdx.x < E) g_count[threadIdx.x] = 0; }

__global__ void offs_kernel() {
    if (threadIdx.x == 0) {
        int o = 0;
        for (int e = 0; e < E; e++) { g_offs[e] = o; o += g_count[e]; }
    }
}

// ---------------- router ----------------
__global__ __launch_bounds__(256) void router_kernel(const float* __restrict__ x,
                                                     const float* __restrict__ gw,
                                                     const int* __restrict__ topk_ptr) {
    const int token = blockIdx.x;
    const float* xr = x + (size_t)token * H;
    float p[E];
#pragma unroll
    for (int e = 0; e < E; e++) p[e] = 0.f;
    for (int h = threadIdx.x; h < H; h += blockDim.x) {
        const float xv = xr[h];
#pragma unroll
        for (int e = 0; e < E; e++) p[e] += xv * gw[e * H + h];
    }
#pragma unroll
    for (int e = 0; e < E; e++)
#pragma unroll
        for (int o = 16; o > 0; o >>= 1) p[e] += __shfl_xor_sync(0xffffffffu, p[e], o);

    __shared__ float sp[8][E];
    const int warp = threadIdx.x >> 5, lane = threadIdx.x & 31;
    if (lane == 0)
#pragma unroll
        for (int e = 0; e < E; e++) sp[warp][e] = p[e];
    __syncthreads();

    if (threadIdx.x == 0) {
        float lg[E];
#pragma unroll
        for (int e = 0; e < E; e++) {
            float s = 0.f;
            for (int w = 0; w < 8; w++) s += sp[w][e];
            lg[e] = s;
        }
        float mx = lg[0];
#pragma unroll
        for (int e = 1; e < E; e++) mx = fmaxf(mx, lg[e]);
        float pr[E], psum = 0.f;
#pragma unroll
        for (int e = 0; e < E; e++) { pr[e] = expf(lg[e] - mx); psum += pr[e]; }
#pragma unroll
        for (int e = 0; e < E; e++) pr[e] /= psum;

        int k = topk_ptr[0];
        if (k < 1) k = 1;
        if (k > MAXK) k = MAXK;

        bool used[E];
#pragma unroll
        for (int e = 0; e < E; e++) used[e] = false;
        int sel[MAXK]; float sw[MAXK]; float ssum = 0.f;
        for (int j = 0; j < k; j++) {
            int best = -1; float bv = -1.f;
            for (int e = 0; e < E; e++)
                if (!used[e] && pr[e] > bv) { bv = pr[e]; best = e; }
            used[best] = true; sel[j] = best; sw[j] = bv; ssum += bv;
        }
        const float inv = 1.f / ssum;
        for (int j = 0; j < k; j++) {
            const int ee = sel[j];
            const int pos = atomicAdd(&g_count[ee], 1);
            g_tok[ee * NTOK + pos] = token;
            g_wt [ee * NTOK + pos] = sw[j] * inv;
        }
    }
}

// ---------------- tf32 mma.sync grouped GEMM ----------------
// D[128x128] = A[128xK] @ B_e[128xK]^T ; 8 warps (2M x 4N), warp tile 64x32
// B_e = B_src + e*NB*K  (NB = rows of B per expert)  <-- R6 bug: this offset was missing
// IS_UP: A = gathered x rows (A_src), epilogue silu -> g_act (device symbol)
// else : A = g_act (device symbol), epilogue wt*atomicAdd -> out
template <bool IS_UP, int K, int NB>
__global__ __launch_bounds__(256) void mma_gemm_kernel(const float* __restrict__ A_src,
                                                       const float* __restrict__ B_src,
                                                       float* __restrict__ out) {
    const int e   = blockIdx.z;
    const int cnt = g_count[e];
    const int m0  = blockIdx.y * BM;
    if (m0 >= cnt) return;
    const int n0   = blockIdx.x * BN;
    const int base = g_offs[e];

    __shared__ float As[BM][SPAD];
    __shared__ float Bs[BN][SPAD];

    const int tid  = threadIdx.x;
    const int lane = tid & 31;
    const int warp = tid >> 5;
    const int wm   = warp & 1;       // 0..1
    const int wn   = warp >> 1;      // 0..3

    // staging: thread -> (row, 16-float half)
    const int sr = tid >> 1;
    const int sh = (tid & 1) * 16;

    const float* arow = nullptr;
    {
        const int gm = m0 + sr;
        if (gm < cnt) {
            if (IS_UP) arow = A_src + (size_t)g_tok[e * NTOK + gm] * K + sh;
            else       arow = g_act + (size_t)(base + gm) * K + sh;
        }
    }
    // per-expert weight slab (the R6 fix)
    const float* brow = B_src + (size_t)e * NB * K + (size_t)(n0 + sr) * K + sh;

    float acc[4][4][4];
#pragma unroll
    for (int i = 0; i < 4; i++)
#pragma unroll
        for (int j = 0; j < 4; j++)
#pragma unroll
            for (int c = 0; c < 4; c++) acc[i][j][c] = 0.f;

    float pa[16], pb[16];

    // prologue: load slab 0
#pragma unroll
    for (int q = 0; q < 4; q++) {
        float4 va = make_float4(0.f, 0.f, 0.f, 0.f);
        if (arow) va = *(const float4*)(arow + 4 * q);
        pa[4*q] = va.x; pa[4*q+1] = va.y; pa[4*q+2] = va.z; pa[4*q+3] = va.w;
        const float4 vb = *(const float4*)(brow + 4 * q);
        pb[4*q] = vb.x; pb[4*q+1] = vb.y; pb[4*q+2] = vb.z; pb[4*q+3] = vb.w;
    }
#pragma unroll
    for (int q = 0; q < 4; q++) {
        *(float4*)&As[sr][sh + 4*q] = make_float4(to_tf32(pa[4*q]),   to_tf32(pa[4*q+1]),
                                                  to_tf32(pa[4*q+2]), to_tf32(pa[4*q+3]));
        *(float4*)&Bs[sr][sh + 4*q] = make_float4(to_tf32(pb[4*q]),   to_tf32(pb[4*q+1]),
                                                  to_tf32(pb[4*q+2]), to_tf32(pb[4*q+3]));
    }
    __syncthreads();

    const int NS = K / BK;
    for (int s = 0; s < NS; s++) {
        // prefetch next slab into regs (overlaps MMA below)
        if (s + 1 < NS) {
            const int k0 = (s + 1) * BK;
#pragma unroll
            for (int q = 0; q < 4; q++) {
                float4 va = make_float4(0.f, 0.f, 0.f, 0.f);
                if (arow) va = *(const float4*)(arow + k0 + 4 * q);
                pa[4*q] = va.x; pa[4*q+1] = va.y; pa[4*q+2] = va.z; pa[4*q+3] = va.w;
                const float4 vb = *(const float4*)(brow + k0 + 4 * q);
                pb[4*q] = vb.x; pb[4*q+1] = vb.y; pb[4*q+2] = vb.z; pb[4*q+3] = vb.w;
            }
        }

        // compute 4 k-steps of 8
#pragma unroll
        for (int kk = 0; kk < 4; kk++) {
            uint32_t a[4][4], b[4][2];
            const int ac = kk * 8 + (lane & 3);
#pragma unroll
            for (int mi = 0; mi < 4; mi++) {
                const int ar = wm * 64 + mi * 16 + (lane >> 2);
                a[mi][0] = __float_as_uint(As[ar    ][ac    ]);
                a[mi][1] = __float_as_uint(As[ar + 8][ac    ]);
                a[mi][2] = __float_as_uint(As[ar    ][ac + 4]);
                a[mi][3] = __float_as_uint(As[ar + 8][ac + 4]);
            }
#pragma unroll
            for (int nj = 0; nj < 4; nj++) {
                const int bn = wn * 32 + nj * 8 + (lane >> 2);
                b[nj][0] = __float_as_uint(Bs[bn][ac    ]);
                b[nj][1] = __float_as_uint(Bs[bn][ac + 4]);
            }
#pragma unroll
            for (int mi = 0; mi < 4; mi++)
#pragma unroll
                for (int nj = 0; nj < 4; nj++)
                    MMA_TF32(acc[mi][nj], a[mi], b[nj]);
        }
        __syncthreads();

        if (s + 1 < NS) {
#pragma unroll
            for (int q = 0; q < 4; q++) {
                *(float4*)&As[sr][sh + 4*q] = make_float4(to_tf32(pa[4*q]),   to_tf32(pa[4*q+1]),
                                                          to_tf32(pa[4*q+2]), to_tf32(pa[4*q+3]));
                *(float4*)&Bs[sr][sh + 4*q] = make_float4(to_tf32(pb[4*q]),   to_tf32(pb[4*q+1]),
                                                          to_tf32(pb[4*q+2]), to_tf32(pb[4*q+3]));
            }
            __syncthreads();
        }
    }

    // epilogue
#pragma unroll
    for (int mi = 0; mi < 4; mi++) {
        const int r0 = m0 + wm * 64 + mi * 16 + (lane >> 2);
#pragma unroll
        for (int hf = 0; hf < 2; hf++) {
            const int m = r0 + hf * 8;
            if (m < cnt) {
                if (IS_UP) {
                    float* dstrow = g_act + (size_t)(base + m) * F;
#pragma unroll
                    for (int nj = 0; nj < 4; nj++) {
                        const int c = n0 + wn * 32 + nj * 8 + 2 * (lane & 3);
                        const float v0 = acc[mi][nj][hf * 2];
                        const float v1 = acc[mi][nj][hf * 2 + 1];
                        float2 r;
                        r.x = v0 / (1.f + expf(-v0));
                        r.y = v1 / (1.f + expf(-v1));
                        *(float2*)(dstrow + c) = r;
                    }
                } else {
                    const int   tok = g_tok[e * NTOK + m];
                    const float wt  = g_wt [e * NTOK + m];
                    float* dstrow = out + (size_t)tok * H;
#pragma unroll
                    for (int nj = 0; nj < 4; nj++) {
                        const int c = n0 + wn * 32 + nj * 8 + 2 * (lane & 3);
                        atomicAdd(dstrow + c,     acc[mi][nj][hf * 2]     * wt);
                        atomicAdd(dstrow + c + 1, acc[mi][nj][hf * 2 + 1] * wt);
                    }
                }
            }
        }
    }
}

// ---------------- launch ----------------
extern "C" void kernel_launch(void* const* d_in, const int* in_sizes, int n_in,
                              void* d_out, int out_size) {
    const float* x  = (const float*)d_in[0];
    const float* gw = (const float*)d_in[1];
    const float* w1 = (const float*)d_in[2];
    const float* w2 = (const float*)d_in[3];
    const int*   tk = (const int*)d_in[4];
    float* out = (float*)d_out;

    cudaMemsetAsync(out, 0, (size_t)out_size * sizeof(float));
    zero_counts_kernel<<<1, 32>>>();
    router_kernel<<<NTOK, 256>>>(x, gw, tk);
    offs_kernel<<<1, 32>>>();

    dim3 gup(F / BN, NTOK / BM, E);
    mma_gemm_kernel<true,  H, F><<<gup, 256>>>(x, w1, nullptr);

    dim3 gdn(H / BN, NTOK / BM, E);
    mma_gemm_kernel<false, F, H><<<gdn, 256>>>(x /*ignored*/, w2, out);
}